// round 5
// baseline (speedup 1.0000x reference)
#include <cuda_runtime.h>
#include <string.h>

#define D128 128
#define H0 64
#define W0 96
#define HW0 (H0 * W0)   // 6144

// fp32 pyramids (HWD layout). L0 786432, L1 196608, L2 49152, L3 12288.
__device__ __align__(16) float g_f1[1044480];
__device__ __align__(16) float g_f2[1044480];

typedef unsigned long long ull;

__device__ __forceinline__ void fma2(ull& d, ull a, ull b) {
    asm("fma.rn.f32x2 %0, %1, %2, %3;" : "=l"(d) : "l"(a), "l"(b), "l"(d));
}
__device__ __forceinline__ ulonglong2 asu2(float4 v) {
    ulonglong2 r; memcpy(&r, &v, 16); return r;
}

// ---------------------------------------------------------------------------
// Kernel 1: transpose (D, H*W) -> (H*W, D). 64-pixel x 32-channel tiles,
// 2 float4 per thread each direction. blockDim (8,32).
// ---------------------------------------------------------------------------
__global__ __launch_bounds__(256) void transpose_kernel(const float* __restrict__ f1,
                                                        const float* __restrict__ f2) {
    __shared__ float tile[64][33];
    int isF2 = blockIdx.z;
    const float* in  = isF2 ? f2 : f1;
    float*       out = isF2 ? g_f2 : g_f1;
    int pB = blockIdx.x * 64;   // pixel base
    int dB = blockIdx.y * 32;   // channel base
    int tx = threadIdx.x;       // 0..7
    int ty = threadIdx.y;       // 0..31

    // read channel row (dB+ty): two float4 pixel chunks
    const float* src = in + (dB + ty) * HW0 + pB;
    float4 v0 = *(const float4*)(src + 4 * tx);
    float4 v1 = *(const float4*)(src + 32 + 4 * tx);
    tile[4 * tx + 0][ty] = v0.x;  tile[4 * tx + 1][ty] = v0.y;
    tile[4 * tx + 2][ty] = v0.z;  tile[4 * tx + 3][ty] = v0.w;
    tile[32 + 4 * tx + 0][ty] = v1.x;  tile[32 + 4 * tx + 1][ty] = v1.y;
    tile[32 + 4 * tx + 2][ty] = v1.z;  tile[32 + 4 * tx + 3][ty] = v1.w;
    __syncthreads();

    // write pixel rows (pB+ty) and (pB+ty+32): float4 of channels
    float4 w0, w1;
    w0.x = tile[ty][4 * tx + 0];  w0.y = tile[ty][4 * tx + 1];
    w0.z = tile[ty][4 * tx + 2];  w0.w = tile[ty][4 * tx + 3];
    w1.x = tile[ty + 32][4 * tx + 0];  w1.y = tile[ty + 32][4 * tx + 1];
    w1.z = tile[ty + 32][4 * tx + 2];  w1.w = tile[ty + 32][4 * tx + 3];
    *(float4*)(out + (pB + ty) * D128 + dB + 4 * tx) = w0;
    *(float4*)(out + (pB + ty + 32) * D128 + dB + 4 * tx) = w1;
}

// ---------------------------------------------------------------------------
// Kernel 2: all pooled levels from transposed L0, float4-vectorized.
// 64512 float4 outputs per map (L1 49152 + L2 12288 + L3 3072), x2 maps.
// ---------------------------------------------------------------------------
__global__ void pool_all_kernel() {
    int i = blockIdx.x * 256 + threadIdx.x;
    if (i >= 2 * 64512) return;
    int isF2 = (i >= 64512);
    if (isF2) i -= 64512;
    float* base = isF2 ? g_f2 : g_f1;

    int lvl, ooff, idx;   // idx in float4 units
    if (i < 49152)      { lvl = 1; ooff = 786432;  idx = i; }
    else if (i < 61440) { lvl = 2; ooff = 983040;  idx = i - 49152; }
    else                { lvl = 3; ooff = 1032192; idx = i - 61440; }

    int c4 = idx & 31;    // float4 channel index (0..31)
    int pk = idx >> 5;
    int Wl = W0 >> lvl;
    int wo = pk % Wl, ho = pk / Wl;
    int s  = 1 << lvl;
    const float4* in = (const float4*)base + ((ho * s) * W0 + wo * s) * 32 + c4;
    float4 acc = make_float4(0.f, 0.f, 0.f, 0.f);
    for (int dy = 0; dy < s; dy++)
        for (int dx = 0; dx < s; dx++) {
            float4 v = in[(dy * W0 + dx) * 32];
            acc.x += v.x; acc.y += v.y; acc.z += v.z; acc.w += v.w;
        }
    float r = 1.0f / (float)(s * s);
    acc.x *= r; acc.y *= r; acc.z *= r; acc.w *= r;
    ((float4*)(base + ooff))[idx] = acc;
}

// ---------------------------------------------------------------------------
// Kernel 3: fused correlation lookup, all 4 levels. One 128-thread block
// per pixel. Tap addresses precomputed into SMEM; dot products via packed
// fma.rn.f32x2 (8 lanes per position, 4 positions per warp per pass).
// ---------------------------------------------------------------------------
__global__ __launch_bounds__(128) void corr_kernel(const float* __restrict__ coords,
                                                   float* __restrict__ out) {
    // same-SM blocks (bid mod 148) get contiguous work ids -> L1 locality
    int g = (blockIdx.x % 148) * 56 + blockIdx.x / 148;
    if (g >= 8160) return;

    int lvl, p;
    if (g < 6144)       { lvl = 0; p = g; }
    else if (g < 7680)  { lvl = 1; p = g - 6144; }
    else if (g < 8064)  { lvl = 2; p = g - 7680; }
    else                { lvl = 3; p = g - 8064; }

    int loff, ooff;
    switch (lvl) {
        case 0:  loff = 0;       ooff = 0;      break;
        case 1:  loff = 786432;  ooff = 497664; break;
        case 2:  loff = 983040;  ooff = 622080; break;
        default: loff = 1032192; ooff = 653184; break;
    }
    const int Hl = H0 >> lvl, Wl = W0 >> lvl;
    int py = p / Wl, px = p - py * Wl;

    __shared__ float sh_c[2];
    __shared__ int   sh_addr[112];
    __shared__ float sh_dot[112];

    int t    = threadIdx.x;
    int w    = t >> 5;
    int lane = t & 31;
    int sub  = lane & 7;
    int quad = lane >> 3;

    // --- coords at this level (jax.image.resize linear antialias semantics)
    if (t < 2) {
        float c;
        if (lvl == 0) {
            c = coords[t * HW0 + p];
        } else {
            int   f    = 1 << lvl;
            float invf = 1.0f / (float)f;
            float sy = ((float)py + 0.5f) * (float)f - 0.5f;
            float sx = ((float)px + 0.5f) * (float)f - 0.5f;
            int jylo = max(0,      (int)floorf(sy - (float)f) + 1);
            int jyhi = min(H0 - 1, (int)floorf(sy + (float)f));
            int jxlo = max(0,      (int)floorf(sx - (float)f) + 1);
            int jxhi = min(W0 - 1, (int)floorf(sx + (float)f));
            float wyTot = 0.f, wxTot = 0.f;
            for (int j = jylo; j <= jyhi; j++) wyTot += 1.f - fabsf(sy - (float)j) * invf;
            for (int j = jxlo; j <= jxhi; j++) wxTot += 1.f - fabsf(sx - (float)j) * invf;
            const float* cc = coords + t * HW0;
            float acc = 0.f;
            for (int jy = jylo; jy <= jyhi; jy++) {
                float wy = 1.f - fabsf(sy - (float)jy) * invf;
                float ra = 0.f;
                for (int jx = jxlo; jx <= jxhi; jx++)
                    ra += (1.f - fabsf(sx - (float)jx) * invf) * cc[jy * W0 + jx];
                acc += wy * ra;
            }
            c = acc / (wyTot * wxTot) * invf;
        }
        sh_c[t] = c;
    }

    // --- f1 fp32 chunks (channels {4s..4s+3, 32+4s.., 64+4s.., 96+4s..})
    const float4* f1v = (const float4*)(g_f1 + loff + p * D128);
    ulonglong2 a0 = asu2(f1v[sub]);
    ulonglong2 a1 = asu2(f1v[8 + sub]);
    ulonglong2 a2 = asu2(f1v[16 + sub]);
    ulonglong2 a3 = asu2(f1v[24 + sub]);

    __syncthreads();

    float cx = sh_c[0], cy = sh_c[1];
    int ix = (int)floorf(cx);
    int iy = (int)floorf(cy);

    // --- precompute clamped tap base addresses (float4 units)
    if (t < 100) {
        int ty = t / 10, tx = t - ty * 10;
        int gy = min(max(iy + ty - 4, 0), Hl - 1);
        int gx = min(max(ix + tx - 4, 0), Wl - 1);
        sh_addr[t] = (gy * Wl + gx) * 32;
    }
    __syncthreads();

    const float4* f2base = (const float4*)(g_f2 + loff);

    // --- 100 corner dots: 7 passes x (4 warps x 4 positions)
#pragma unroll
    for (int j = 0; j < 7; j++) {
        int pos  = j * 16 + w * 4 + quad;      // 0..111
        int posc = min(pos, 99);
        const float4* q = f2base + sh_addr[posc];
        ulonglong2 q0 = asu2(q[sub]);
        ulonglong2 q1 = asu2(q[8 + sub]);
        ulonglong2 q2 = asu2(q[16 + sub]);
        ulonglong2 q3 = asu2(q[24 + sub]);
        ull acc = 0ULL;
        fma2(acc, a0.x, q0.x); fma2(acc, a0.y, q0.y);
        fma2(acc, a1.x, q1.x); fma2(acc, a1.y, q1.y);
        fma2(acc, a2.x, q2.x); fma2(acc, a2.y, q2.y);
        fma2(acc, a3.x, q3.x); fma2(acc, a3.y, q3.y);
        float2 fr; memcpy(&fr, &acc, 8);
        float s = fr.x + fr.y;
        s += __shfl_xor_sync(0xffffffffu, s, 1);
        s += __shfl_xor_sync(0xffffffffu, s, 2);
        s += __shfl_xor_sync(0xffffffffu, s, 4);
        if (sub == 0 && pos < 100) sh_dot[pos] = s;
    }
    __syncthreads();

    // --- bilinear combine, k = dxi*9 + dyi (x slow, y fast)
    if (t < 81) {
        int dxi = t / 9, dyi = t - dxi * 9;
        float xq = fminf(fmaxf(cx + (float)(dxi - 4), 0.f), (float)(Wl - 1));
        float yq = fminf(fmaxf(cy + (float)(dyi - 4), 0.f), (float)(Hl - 1));
        float x0f = floorf(xq), y0f = floorf(yq);
        float wx1 = xq - x0f,  wy1 = yq - y0f;
        float wx0 = 1.f - wx1, wy0 = 1.f - wy1;
        int t0x = min(max((int)x0f - ix + 4, 0), 9), t1x = min(t0x + 1, 9);
        int t0y = min(max((int)y0f - iy + 4, 0), 9), t1y = min(t0y + 1, 9);
        float v = wy0 * (wx0 * sh_dot[t0y * 10 + t0x] + wx1 * sh_dot[t0y * 10 + t1x])
                + wy1 * (wx0 * sh_dot[t1y * 10 + t0x] + wx1 * sh_dot[t1y * 10 + t1x]);
        out[ooff + t * (Hl * Wl) + p] = v * 0.08838834764831845f;  // 1/sqrt(128)
    }
}

// ---------------------------------------------------------------------------
extern "C" void kernel_launch(void* const* d_in, const int* in_sizes, int n_in,
                              void* d_out, int out_size) {
    const float* f1     = (const float*)d_in[0];
    const float* f2     = (const float*)d_in[1];
    const float* coords = (const float*)d_in[2];
    float* out = (float*)d_out;

    transpose_kernel<<<dim3(HW0 / 64, D128 / 32, 2), dim3(8, 32)>>>(f1, f2);
    pool_all_kernel<<<504, 256>>>();
    corr_kernel<<<8288, 128>>>(coords, out);
}

// round 6
// speedup vs baseline: 1.2014x; 1.2014x over previous
#include <cuda_runtime.h>
#include <string.h>

#define D128 128
#define H0 64
#define W0 96
#define HW0 (H0 * W0)   // 6144

// fp32 pyramids (HWD layout). L0 786432, L1 196608, L2 49152, L3 12288.
__device__ __align__(16) float g_f1[1044480];
__device__ __align__(16) float g_f2[1044480];

typedef unsigned long long ull;

__device__ __forceinline__ void fma2(ull& d, ull a, ull b) {
    asm("fma.rn.f32x2 %0, %1, %2, %3;" : "=l"(d) : "l"(a), "l"(b), "l"(d));
}
__device__ __forceinline__ ulonglong2 asu2(float4 v) {
    ulonglong2 r; memcpy(&r, &v, 16); return r;
}

// ---------------------------------------------------------------------------
// Kernel 1: fused transpose + full pyramid build. One block per 8x8 pixel
// tile per map. Loads (D,H,W) source once, emits transposed (HW,D) L0 and
// cascaded 2x2-mean L1/L2/L3 via SMEM. grid (96, 1, 2), block 256.
// ---------------------------------------------------------------------------
__global__ __launch_bounds__(256) void build_kernel(const float* __restrict__ f1,
                                                    const float* __restrict__ f2) {
    __shared__ float s0[8][8][128];   // [y][x][ch] 32KB
    __shared__ float s1[4][4][128];   // 8KB
    __shared__ float s2[2][2][128];   // 2KB
    int map = blockIdx.z;
    const float* in = map ? f2 : f1;
    float* base = map ? g_f2 : g_f1;
    int tx0 = (blockIdx.x % 12) * 8;
    int ty0 = (blockIdx.x / 12) * 8;
    int t = threadIdx.x;
    int d    = t >> 1;   // channel 0..127
    int half = t & 1;    // which float4 of the 8-px row

    // load: 8 rows of 8 px (two float4) for channel d
    float4 v[8];
    const float* src = in + d * HW0 + ty0 * W0 + tx0 + half * 4;
#pragma unroll
    for (int y = 0; y < 8; y++) v[y] = *(const float4*)(src + y * W0);
#pragma unroll
    for (int y = 0; y < 8; y++) {
        int xb = half * 4;
        s0[y][xb + 0][d] = v[y].x;  s0[y][xb + 1][d] = v[y].y;
        s0[y][xb + 2][d] = v[y].z;  s0[y][xb + 3][d] = v[y].w;
    }
    __syncthreads();

    // write transposed L0: 2048 float4, 8 per thread, coalesced
#pragma unroll
    for (int i = 0; i < 8; i++) {
        int idx = i * 256 + t;
        int c4 = idx & 31;
        int px = idx >> 5;          // 0..63
        int y = px >> 3, x = px & 7;
        float4 w = *(float4*)&s0[y][x][c4 * 4];
        int gp = (ty0 + y) * W0 + tx0 + x;
        *(float4*)(base + gp * D128 + c4 * 4) = w;
    }

    // L1: 4x4 px x 128 ch
#pragma unroll
    for (int i = 0; i < 8; i++) {
        int idx = i * 256 + t;      // 0..2047
        int c = idx & 127;
        int px = idx >> 7;          // 0..15
        int y = px >> 2, x = px & 3;
        float r = 0.25f * (s0[2*y][2*x][c] + s0[2*y][2*x+1][c]
                         + s0[2*y+1][2*x][c] + s0[2*y+1][2*x+1][c]);
        s1[y][x][c] = r;
        int gp = (ty0 / 2 + y) * 48 + tx0 / 2 + x;
        base[786432 + gp * D128 + c] = r;
    }
    __syncthreads();

    // L2: 2x2 px x 128 ch
#pragma unroll
    for (int i = 0; i < 2; i++) {
        int idx = i * 256 + t;      // 0..511
        int c = idx & 127;
        int px = idx >> 7;          // 0..3
        int y = px >> 1, x = px & 1;
        float r = 0.25f * (s1[2*y][2*x][c] + s1[2*y][2*x+1][c]
                         + s1[2*y+1][2*x][c] + s1[2*y+1][2*x+1][c]);
        s2[y][x][c] = r;
        int gp = (ty0 / 4 + y) * 24 + tx0 / 4 + x;
        base[983040 + gp * D128 + c] = r;
    }
    __syncthreads();

    // L3: 1 px x 128 ch
    if (t < 128) {
        float r = 0.25f * (s2[0][0][t] + s2[0][1][t] + s2[1][0][t] + s2[1][1][t]);
        int gp = (ty0 / 8) * 12 + tx0 / 8;
        base[1032192 + gp * D128 + t] = r;
    }
}

// ---------------------------------------------------------------------------
// Kernel 2: fused correlation lookup, all 4 levels. 256 threads handle a
// PAIR of adjacent pixels (warps 0-3 -> p, warps 4-7 -> p+1); amortized
// syncs/coords machinery and pairwise-coalesced stores. Dot phase: tap
// addresses precomputed in SMEM, packed fma.rn.f32x2, 8 lanes/position.
// ---------------------------------------------------------------------------
__global__ __launch_bounds__(256) void corr_kernel(const float* __restrict__ coords,
                                                   float* __restrict__ out) {
    // same-SM blocks (bid mod 148) get contiguous work -> L1 locality
    int gq = (blockIdx.x % 148) * 28 + blockIdx.x / 148;
    if (gq >= 4080) return;

    int lvl, q;
    if (gq < 3072)      { lvl = 0; q = gq; }
    else if (gq < 3840) { lvl = 1; q = gq - 3072; }
    else if (gq < 4032) { lvl = 2; q = gq - 3840; }
    else                { lvl = 3; q = gq - 4032; }

    int loff, ooff;
    switch (lvl) {
        case 0:  loff = 0;       ooff = 0;      break;
        case 1:  loff = 786432;  ooff = 497664; break;
        case 2:  loff = 983040;  ooff = 622080; break;
        default: loff = 1032192; ooff = 653184; break;
    }
    const int Hl = H0 >> lvl, Wl = W0 >> lvl;

    int t    = threadIdx.x;
    int side = t >> 7;          // which pixel of the pair
    int tt   = t & 127;
    int p    = 2 * q + side;
    int py = p / Wl, px = p - py * Wl;

    __shared__ float sh_c[2][2];
    __shared__ int   sh_addr[2][112];
    __shared__ float sh_dot[2][112];

    int w    = tt >> 5;         // warp-within-side 0..3
    int lane = tt & 31;
    int sub  = lane & 7;
    int quad = lane >> 3;

    // --- coords at this level (jax.image.resize linear antialias semantics)
    if (tt < 2) {
        float c;
        if (lvl == 0) {
            c = coords[tt * HW0 + p];
        } else {
            int   f    = 1 << lvl;
            float invf = 1.0f / (float)f;
            float sy = ((float)py + 0.5f) * (float)f - 0.5f;
            float sx = ((float)px + 0.5f) * (float)f - 0.5f;
            int jylo = max(0,      (int)floorf(sy - (float)f) + 1);
            int jyhi = min(H0 - 1, (int)floorf(sy + (float)f));
            int jxlo = max(0,      (int)floorf(sx - (float)f) + 1);
            int jxhi = min(W0 - 1, (int)floorf(sx + (float)f));
            float wyTot = 0.f, wxTot = 0.f;
            for (int j = jylo; j <= jyhi; j++) wyTot += 1.f - fabsf(sy - (float)j) * invf;
            for (int j = jxlo; j <= jxhi; j++) wxTot += 1.f - fabsf(sx - (float)j) * invf;
            const float* cc = coords + tt * HW0;
            float acc = 0.f;
            for (int jy = jylo; jy <= jyhi; jy++) {
                float wy = 1.f - fabsf(sy - (float)jy) * invf;
                float ra = 0.f;
                for (int jx = jxlo; jx <= jxhi; jx++)
                    ra += (1.f - fabsf(sx - (float)jx) * invf) * cc[jy * W0 + jx];
                acc += wy * ra;
            }
            c = acc / (wyTot * wxTot) * invf;
        }
        sh_c[side][tt] = c;
    }

    // --- f1 fp32 chunks for this lane (channels 8*sub.., 64+8*sub.. pattern)
    const float4* f1v = (const float4*)(g_f1 + loff + p * D128);
    ulonglong2 a0 = asu2(f1v[sub]);
    ulonglong2 a1 = asu2(f1v[8 + sub]);
    ulonglong2 a2 = asu2(f1v[16 + sub]);
    ulonglong2 a3 = asu2(f1v[24 + sub]);

    __syncthreads();

    float cx = sh_c[side][0], cy = sh_c[side][1];
    int ix = (int)floorf(cx);
    int iy = (int)floorf(cy);

    // --- precompute clamped tap base addresses (float4 units)
    if (tt < 100) {
        int ty = tt / 10, tx = tt - ty * 10;
        int gy = min(max(iy + ty - 4, 0), Hl - 1);
        int gx = min(max(ix + tx - 4, 0), Wl - 1);
        sh_addr[side][tt] = (gy * Wl + gx) * 32;
    }
    __syncthreads();

    const float4* f2base = (const float4*)(g_f2 + loff);

    // --- 100 corner dots per side: 7 passes x (4 warps x 4 positions)
#pragma unroll
    for (int j = 0; j < 7; j++) {
        int pos  = j * 16 + w * 4 + quad;     // 0..111
        int posc = min(pos, 99);
        const float4* qv = f2base + sh_addr[side][posc];
        ulonglong2 q0 = asu2(qv[sub]);
        ulonglong2 q1 = asu2(qv[8 + sub]);
        ulonglong2 q2 = asu2(qv[16 + sub]);
        ulonglong2 q3 = asu2(qv[24 + sub]);
        ull acc = 0ULL;
        fma2(acc, a0.x, q0.x); fma2(acc, a0.y, q0.y);
        fma2(acc, a1.x, q1.x); fma2(acc, a1.y, q1.y);
        fma2(acc, a2.x, q2.x); fma2(acc, a2.y, q2.y);
        fma2(acc, a3.x, q3.x); fma2(acc, a3.y, q3.y);
        float2 fr; memcpy(&fr, &acc, 8);
        float s = fr.x + fr.y;
        s += __shfl_xor_sync(0xffffffffu, s, 1);
        s += __shfl_xor_sync(0xffffffffu, s, 2);
        s += __shfl_xor_sync(0xffffffffu, s, 4);
        if (sub == 0 && pos < 100) sh_dot[side][pos] = s;
    }
    __syncthreads();

    // --- bilinear combine: threads t<162 -> (k = t/2, sd = t&1).
    // Pairwise store: 8B contiguous per output line.
    if (t < 162) {
        int k  = t >> 1;
        int sd = t & 1;
        float cx2 = sh_c[sd][0], cy2 = sh_c[sd][1];
        int ix2 = (int)floorf(cx2);
        int iy2 = (int)floorf(cy2);
        int dxi = k / 9, dyi = k - dxi * 9;
        float xq = fminf(fmaxf(cx2 + (float)(dxi - 4), 0.f), (float)(Wl - 1));
        float yq = fminf(fmaxf(cy2 + (float)(dyi - 4), 0.f), (float)(Hl - 1));
        float x0f = floorf(xq), y0f = floorf(yq);
        float wx1 = xq - x0f,  wy1 = yq - y0f;
        float wx0 = 1.f - wx1, wy0 = 1.f - wy1;
        int t0x = min(max((int)x0f - ix2 + 4, 0), 9), t1x = min(t0x + 1, 9);
        int t0y = min(max((int)y0f - iy2 + 4, 0), 9), t1y = min(t0y + 1, 9);
        float v = wy0 * (wx0 * sh_dot[sd][t0y * 10 + t0x] + wx1 * sh_dot[sd][t0y * 10 + t1x])
                + wy1 * (wx0 * sh_dot[sd][t1y * 10 + t0x] + wx1 * sh_dot[sd][t1y * 10 + t1x]);
        out[ooff + k * (Hl * Wl) + 2 * q + sd] = v * 0.08838834764831845f;  // 1/sqrt(128)
    }
}

// ---------------------------------------------------------------------------
extern "C" void kernel_launch(void* const* d_in, const int* in_sizes, int n_in,
                              void* d_out, int out_size) {
    const float* f1     = (const float*)d_in[0];
    const float* f2     = (const float*)d_in[1];
    const float* coords = (const float*)d_in[2];
    float* out = (float*)d_out;

    build_kernel<<<dim3(96, 1, 2), 256>>>(f1, f2);
    // 148 * 28 = 4144 blocks cover 4080 pixel-pairs with SM-contiguous mapping
    corr_kernel<<<4144, 256>>>(coords, out);
}